// round 15
// baseline (speedup 1.0000x reference)
#include <cuda_runtime.h>
#include <cuda_fp16.h>
#include <cstdint>
#include <cstddef>

#define IN_F   1024
#define OUT_F  1024
#define POP    64
#define MROWS  16384

#define BM 128
#define BN 128
#define BK 64
#define THREADS 288                // uniform block size (8 consumers + producer)
#define NCH (IN_F / BK)            // 16 k-chunks

// grid layout: [0,1024) w-rows | [1024,5120) x-groups | [5120,5124) bias | [5124,6148) gemm
#define WBLK  1024
#define XBLK  4096
#define BBLK  4
#define GEMM0 (WBLK + XBLK + BBLK)          // 5124
#define NGEMM 1024

// smem: fp16 rows of 64 elems (128B) + 16B pad = 144B stride (conflict-free)
#define ROWB     144
#define A_OFF    0
#define B_OFF    18432
#define STAGE_SZ 36864
#define NSTAGE   3
#define SM_MBAR  0
#define SM_TILE0 1024
#define SMEM_TOTAL (SM_TILE0 + NSTAGE * STAGE_SZ)   // 111616 B -> 2 blocks/SM

// ---------------- scratch (device globals; allocation is forbidden) --------
__device__ __align__(16) __half g_x[(size_t)MROWS * IN_F];
__device__ __align__(16) __half g_w[(size_t)OUT_F * IN_F];
__device__ float g_beff[OUT_F];
// gating counters (zero-init; self-resetting each run for graph replay)
__device__ uint32_t g_wcnt[8], g_wack[8];      // per n-block: target 128
__device__ uint32_t g_xcnt[128], g_xack[128];  // per m-block: target 32
__device__ uint32_t g_bcnt, g_back;            // bias: target 4 / 1024

// ---------------- PTX helpers (portable to plain sm_103 target) ------------
__device__ __forceinline__ uint32_t smem_u32(const void* p) {
    uint32_t a;
    asm("{ .reg .u64 t; cvta.to.shared.u64 t, %1; cvt.u32.u64 %0, t; }" : "=r"(a) : "l"(p));
    return a;
}
__device__ __forceinline__ uint32_t ld_acq_gpu(const uint32_t* p) {
    uint32_t v;
    asm volatile("ld.acquire.gpu.global.u32 %0, [%1];" : "=r"(v) : "l"(p) : "memory");
    return v;
}
#define CP16(dst_u32, gptr) \
    asm volatile("cp.async.cg.shared.global [%0], [%1], 16;" :: "r"(dst_u32), "l"(gptr) : "memory")
// .noinc is LOAD-BEARING (default form deadlocks preset-count barriers)
#define CPASYNC_MBAR_ARRIVE_NOINC(a) \
    asm volatile("cp.async.mbarrier.arrive.noinc.shared.b64 [%0];" :: "r"(a) : "memory")
#define MBAR_INIT(a, c) \
    asm volatile("mbarrier.init.shared.b64 [%0], %1;" :: "r"(a), "r"(c) : "memory")
#define MBAR_ARRIVE(a) do { unsigned long long _st;                              \
    asm volatile("mbarrier.arrive.shared.b64 %0, [%1];"                          \
        : "=l"(_st) : "r"(a) : "memory"); (void)_st; } while (0)
#define MBAR_WAIT_PARITY(addr, par) do {                                         \
    uint32_t _m = (addr); uint32_t _p = (par); uint32_t _done;                   \
    asm volatile("{\n\t.reg .pred p;\n\t"                                        \
        "mbarrier.try_wait.parity.acquire.cta.shared::cta.b64 p, [%1], %2;\n\t"  \
        "selp.b32 %0, 1, 0, p;\n\t}" : "=r"(_done) : "r"(_m), "r"(_p) : "memory"); \
    if (!_done) {                                                                \
        asm volatile("{\n\t.reg .pred P1;\n\tWL_%=: \n\t"                        \
            "mbarrier.try_wait.parity.acquire.cta.shared::cta.b64 P1, [%0], %1, 0x989680;\n\t" \
            "@P1 bra.uni WD_%=;\n\tbra.uni WL_%=;\n\tWD_%=:\n\t}"                \
            :: "r"(_m), "r"(_p) : "memory");                                     \
    } } while (0)

#define LDSM4(r0, r1, r2, r3, addr)                                              \
    asm volatile("ldmatrix.sync.aligned.m8n8.x4.shared.b16 {%0,%1,%2,%3}, [%4];" \
        : "=r"(r0), "=r"(r1), "=r"(r2), "=r"(r3) : "r"(addr))

__device__ __forceinline__ void mma16816(float* d, const uint32_t* a, const uint32_t* b) {
    asm volatile(
        "mma.sync.aligned.m16n8k16.row.col.f32.f16.f16.f32 "
        "{%0,%1,%2,%3}, {%4,%5,%6,%7}, {%8,%9}, {%0,%1,%2,%3};"
        : "+f"(d[0]), "+f"(d[1]), "+f"(d[2]), "+f"(d[3])
        : "r"(a[0]), "r"(a[1]), "r"(a[2]), "r"(a[3]), "r"(b[0]), "r"(b[1]));
}

// ---------------------------------------------------------------------------
// Fused kernel: prep blocks first in grid (row-contiguous R12 patterns),
// GEMM CTAs last. GEMM producers gate on per-block counters; natural
// grid-order scheduling gives tail overlap without starving prep.
// ---------------------------------------------------------------------------
__global__ __launch_bounds__(THREADS, 2)
void fused_kernel(const float* __restrict__ weight,
                  const float* __restrict__ scale,
                  const float* __restrict__ wp,
                  const float* __restrict__ x,
                  const float* __restrict__ bias,
                  const float* __restrict__ bp,
                  float* __restrict__ out) {
    extern __shared__ char smem[];
    const int b   = blockIdx.x;
    const int tid = threadIdx.x;

    if (b < WBLK) {
        // ===== w_eff row b: weight + sum_i s_i*wp_i (fp32) -> fp16 =====
        float* ss = reinterpret_cast<float*>(smem);
        if (tid < POP) ss[tid] = scale[tid];
        __syncthreads();
        if (tid < 256) {
            size_t base = ((size_t)b * 256 + tid) * 4;
            float4 acc = *reinterpret_cast<const float4*>(weight + base);
#pragma unroll 8
            for (int i = 0; i < POP; i++) {
                const float s = ss[i];
                float4 p = *reinterpret_cast<const float4*>(wp + ((size_t)i << 20) + base);
                acc.x += s * p.x; acc.y += s * p.y; acc.z += s * p.z; acc.w += s * p.w;
            }
            __half h[4] = {__float2half_rn(acc.x), __float2half_rn(acc.y),
                           __float2half_rn(acc.z), __float2half_rn(acc.w)};
            *reinterpret_cast<uint2*>(g_w + base) = *reinterpret_cast<uint2*>(h);
        }
        __threadfence();
        __syncthreads();
        if (tid == 0) atomicAdd(&g_wcnt[b >> 7], 1u);   // row b -> n-block b/128
        return;
    }
    if (b < WBLK + XBLK) {
        // ===== x -> fp16, rows [4*(b-WBLK), +4): 16 elems/thread =====
        const int xb = b - WBLK;
        if (tid < 256) {
            size_t base = ((size_t)xb * 256 + tid) * 16;
#pragma unroll
            for (int q = 0; q < 2; q++) {
                float4 a = *reinterpret_cast<const float4*>(x + base + q * 8);
                float4 c = *reinterpret_cast<const float4*>(x + base + q * 8 + 4);
                __half h[8] = {__float2half_rn(a.x), __float2half_rn(a.y),
                               __float2half_rn(a.z), __float2half_rn(a.w),
                               __float2half_rn(c.x), __float2half_rn(c.y),
                               __float2half_rn(c.z), __float2half_rn(c.w)};
                *reinterpret_cast<uint4*>(g_x + base + q * 8) = *reinterpret_cast<uint4*>(h);
            }
        }
        __threadfence();
        __syncthreads();
        if (tid == 0) atomicAdd(&g_xcnt[xb >> 5], 1u);  // 32 x-blocks per m-block
        return;
    }
    if (b < GEMM0) {
        // ===== bias =====
        if (tid < 256) {
            int j = (b - WBLK - XBLK) * 256 + tid;
            float acc = bias[j];
#pragma unroll 8
            for (int i = 0; i < POP; i++) acc += scale[i] * bp[i * OUT_F + j];
            g_beff[j] = acc;
        }
        __threadfence();
        __syncthreads();
        if (tid == 0) atomicAdd(&g_bcnt, 1u);
        return;
    }

    // ===================== GEMM CTA (R14 body) =====================
    const int fb   = b - GEMM0;
    const int bx   = fb & 7, by = fb >> 3;
    const int m0   = by * BM, n0 = bx * BN;
    const uint32_t sb = smem_u32(smem);
    const int wid  = tid >> 5;
    const int lane = tid & 31;

    const uint32_t mb_full  = sb + SM_MBAR;
    const uint32_t mb_empty = sb + SM_MBAR + 24;

    if (tid == 0) {
#pragma unroll
        for (int s = 0; s < NSTAGE; s++) {
            MBAR_INIT(mb_full + 8 * s, 32);
            MBAR_INIT(mb_empty + 8 * s, 256);
        }
    }
    __syncthreads();

    if (wid == 8) {
        // ---- producer: gate once on prep counters, then R14 protocol
        if (lane == 0) {
            while (ld_acq_gpu(&g_wcnt[bx]) < 128u) __nanosleep(512);
            while (ld_acq_gpu(&g_xcnt[by]) < 32u)  __nanosleep(512);
            if (atomicAdd(&g_wack[bx], 1u) == 127u) { g_wcnt[bx] = 0u; g_wack[bx] = 0u; }
            if (atomicAdd(&g_xack[by], 1u) == 7u)   { g_xcnt[by] = 0u; g_xack[by] = 0u; }
        }
        __syncwarp();
        for (int kt = 0; kt < NCH; kt++) {
            const int s = kt % NSTAGE, u = kt / NSTAGE;
            if (u > 0) { MBAR_WAIT_PARITY(mb_empty + 8 * s, (u - 1) & 1); }
            const uint32_t st = sb + SM_TILE0 + s * STAGE_SZ;
            const int krow = kt * BK;
#pragma unroll
            for (int it = 0; it < 32; it++) {       // A: 1024 16B units
                int uu = it * 32 + lane, row = uu >> 3, gg = uu & 7;
                CP16(st + A_OFF + (uint32_t)(row * ROWB + gg * 16),
                     g_x + (size_t)(m0 + row) * IN_F + krow + gg * 8);
            }
#pragma unroll
            for (int it = 0; it < 32; it++) {       // B: 1024 16B units
                int uu = it * 32 + lane, row = uu >> 3, gg = uu & 7;
                CP16(st + B_OFF + (uint32_t)(row * ROWB + gg * 16),
                     g_w + (size_t)(n0 + row) * IN_F + krow + gg * 8);
            }
            CPASYNC_MBAR_ARRIVE_NOINC(mb_full + 8 * s);
        }
        return;
    }

    // ---- consumers (warps 0-7), warp tile 64x32
    const int wm = wid & 1;
    const int wn = wid >> 1;

    float acc[4][4][4];
#pragma unroll
    for (int a = 0; a < 4; a++)
#pragma unroll
        for (int bb = 0; bb < 4; bb++)
#pragma unroll
            for (int c = 0; c < 4; c++) acc[a][bb][c] = 0.0f;

    const int g = lane >> 3, r = lane & 7;
    const uint32_t a_row_off = (uint32_t)((wm * 64 + (g & 1) * 8 + r) * ROWB);
    const uint32_t a_k_off   = (uint32_t)((g >> 1) * 16);
    const uint32_t b_row_off = (uint32_t)((wn * 32 + (g >> 1) * 8 + r) * ROWB);
    const uint32_t b_k_off   = (uint32_t)((g & 1) * 16);

    for (int kt = 0; kt < NCH; kt++) {
        const int s = kt % NSTAGE, u = kt / NSTAGE;
        MBAR_WAIT_PARITY(mb_full + 8 * s, u & 1);

        const uint32_t st = sb + SM_TILE0 + s * STAGE_SZ;
#pragma unroll
        for (int ks = 0; ks < 4; ks++) {
            uint32_t ah[4][4];
#pragma unroll
            for (int mt = 0; mt < 4; mt++) {
                uint32_t aaddr = st + A_OFF + a_row_off + (uint32_t)(mt * 16 * ROWB)
                               + a_k_off + (uint32_t)(ks * 32);
                LDSM4(ah[mt][0], ah[mt][1], ah[mt][2], ah[mt][3], aaddr);
            }
#pragma unroll
            for (int np = 0; np < 2; np++) {
                uint32_t bh[4];
                uint32_t baddr = st + B_OFF + b_row_off + (uint32_t)(np * 16 * ROWB)
                               + b_k_off + (uint32_t)(ks * 32);
                LDSM4(bh[0], bh[1], bh[2], bh[3], baddr);
#pragma unroll
                for (int mt = 0; mt < 4; mt++) {
                    mma16816(acc[mt][2 * np],     ah[mt], bh);
                    mma16816(acc[mt][2 * np + 1], ah[mt], bh + 2);
                }
            }
        }
        MBAR_ARRIVE(mb_empty + 8 * s);
    }

    // ---- epilogue: gate on bias, then R14 stores
    if (lane == 0) { while (ld_acq_gpu(&g_bcnt) < 4u) __nanosleep(256); }
    __syncwarp();
    if (tid == 0) {
        if (atomicAdd(&g_back, 1u) == (uint32_t)(NGEMM - 1)) { g_bcnt = 0u; g_back = 0u; }
    }
    const int erow = lane >> 2;
    const int ecol = 2 * (lane & 3);
#pragma unroll
    for (int mt = 0; mt < 4; mt++) {
        const int mrow = m0 + wm * 64 + mt * 16 + erow;
#pragma unroll
        for (int j = 0; j < 4; j++) {
            const int col = n0 + wn * 32 + j * 8 + ecol;
            const float b0 = g_beff[col], b1 = g_beff[col + 1];
            float2 v0 = make_float2(acc[mt][j][0] + b0, acc[mt][j][1] + b1);
            float2 v1 = make_float2(acc[mt][j][2] + b0, acc[mt][j][3] + b1);
            *reinterpret_cast<float2*>(out + (size_t)mrow * OUT_F + col)       = v0;
            *reinterpret_cast<float2*>(out + (size_t)(mrow + 8) * OUT_F + col) = v1;
        }
    }
}

// ---------------------------------------------------------------------------
// Launch. Inputs identified BY ELEMENT COUNT (all unique, order-independent).
// fp16 inputs arrive as fp32 on device (confirmed R3).
// ---------------------------------------------------------------------------
extern "C" void kernel_launch(void* const* d_in, const int* in_sizes, int n_in,
                              void* d_out, int out_size) {
    const float *x = nullptr, *weight = nullptr, *bias = nullptr,
                *scale = nullptr, *wp = nullptr, *bp = nullptr;
    for (int i = 0; i < n_in; i++) {
        switch (in_sizes[i]) {
            case 16777216: x      = (const float*)d_in[i]; break;
            case 1048576:  weight = (const float*)d_in[i]; break;
            case 1024:     bias   = (const float*)d_in[i]; break;
            case 64:       scale  = (const float*)d_in[i]; break;
            case 67108864: wp     = (const float*)d_in[i]; break;
            case 65536:    bp     = (const float*)d_in[i]; break;
            default: break;
        }
    }
    float* out = (float*)d_out;

    cudaFuncSetAttribute(fused_kernel,
                         cudaFuncAttributeMaxDynamicSharedMemorySize, SMEM_TOTAL);

    fused_kernel<<<GEMM0 + NGEMM, THREADS, SMEM_TOTAL>>>(
        weight, scale, wp, x, bias, bp, out);
}